// round 1
// baseline (speedup 1.0000x reference)
#include <cuda_runtime.h>

// SSIM loss, fused separable 11x11 gaussian blur + ssim map + mean reduce.
// Input: img1, img2 : [32,3,512,512] fp32. Output: scalar fp32.

#define IMG      512
#define TILE_W   64
#define TILE_H   32
#define HALO     5
#define IN_W     74          // TILE_W + 2*HALO
#define IN_WP    76          // padded row stride (16B aligned rows)
#define IN_H     42          // TILE_H + 2*HALO
#define NTHREADS 256
#define HPLANE   (IN_H * TILE_W)   // 2688 floats per blurred field

// smem: 2 raw tiles (IN_H*IN_WP each) + 5 horizontally-blurred fields (IN_H*TILE_W each)
#define SMEM_FLOATS (2 * IN_H * IN_WP + 5 * HPLANE)
#define SMEM_BYTES  (SMEM_FLOATS * 4)

__device__ double g_sum;

// 1D gaussian, sigma=1.5, K=11, normalized (matches reference within fp32 noise)
__device__ __forceinline__ float gw(int k) {
    const float W[11] = {
        0.00102838f, 0.00759877f, 0.03600077f, 0.10936069f, 0.21300554f,
        0.26601173f,
        0.21300554f, 0.10936069f, 0.03600077f, 0.00759877f, 0.00102838f
    };
    return W[k];
}

__global__ void ssim_zero() { g_sum = 0.0; }

__global__ __launch_bounds__(NTHREADS, 2)
void ssim_main(const float* __restrict__ img1, const float* __restrict__ img2) {
    extern __shared__ float smem[];
    float* s1 = smem;                       // raw x1 tile [IN_H][IN_WP]
    float* s2 = smem + IN_H * IN_WP;        // raw x2 tile
    float* sh = smem + 2 * IN_H * IN_WP;    // 5 fields [IN_H][TILE_W]

    const int tid = threadIdx.x;
    const int gx0 = blockIdx.x * TILE_W - HALO;
    const int gy0 = blockIdx.y * TILE_H - HALO;
    const size_t pbase = (size_t)blockIdx.z * (IMG * IMG);
    const float* p1 = img1 + pbase;
    const float* p2 = img2 + pbase;

    // ---- Phase 1: global -> smem, apply (v+1)*0.5, zero-pad out of bounds ----
    for (int idx = tid; idx < IN_H * IN_WP; idx += NTHREADS) {
        int r = idx / IN_WP;
        int c = idx - r * IN_WP;
        int gx = gx0 + c;
        int gy = gy0 + r;
        float v1 = 0.f, v2 = 0.f;
        if (c < IN_W && gx >= 0 && gx < IMG && gy >= 0 && gy < IMG) {
            int o = gy * IMG + gx;
            v1 = (p1[o] + 1.f) * 0.5f;
            v2 = (p2[o] + 1.f) * 0.5f;
        }
        s1[idx] = v1;
        s2[idx] = v2;
    }
    __syncthreads();

    // ---- Phase 2: horizontal 11-tap blur of 5 fields, 4 output cols / task ----
    // tasks: 42 rows x 16 col-groups = 672
    for (int t = tid; t < IN_H * 16; t += NTHREADS) {
        int row = t >> 4;
        int c0  = (t & 15) << 2;

        float a[16], b[16];
        {
            const float4* a4 = (const float4*)(s1 + row * IN_WP + c0);
            const float4* b4 = (const float4*)(s2 + row * IN_WP + c0);
            ((float4*)a)[0] = a4[0]; ((float4*)a)[1] = a4[1];
            ((float4*)a)[2] = a4[2]; ((float4*)a)[3] = a4[3];
            ((float4*)b)[0] = b4[0]; ((float4*)b)[1] = b4[1];
            ((float4*)b)[2] = b4[2]; ((float4*)b)[3] = b4[3];
        }

        float m1[4]  = {0.f, 0.f, 0.f, 0.f};
        float m2[4]  = {0.f, 0.f, 0.f, 0.f};
        float q11[4] = {0.f, 0.f, 0.f, 0.f};
        float q22[4] = {0.f, 0.f, 0.f, 0.f};
        float q12[4] = {0.f, 0.f, 0.f, 0.f};

        #pragma unroll
        for (int i = 0; i < 14; i++) {
            float fa = a[i], fb = b[i];
            float faa = fa * fa, fbb = fb * fb, fab = fa * fb;
            #pragma unroll
            for (int j = 0; j < 4; j++) {
                int k = i - j;
                if (k >= 0 && k < 11) {
                    float w = gw(k);
                    m1[j]  = fmaf(fa,  w, m1[j]);
                    m2[j]  = fmaf(fb,  w, m2[j]);
                    q11[j] = fmaf(faa, w, q11[j]);
                    q22[j] = fmaf(fbb, w, q22[j]);
                    q12[j] = fmaf(fab, w, q12[j]);
                }
            }
        }

        float* hb = sh + row * TILE_W + c0;
        *(float4*)(hb + 0 * HPLANE) = make_float4(m1[0],  m1[1],  m1[2],  m1[3]);
        *(float4*)(hb + 1 * HPLANE) = make_float4(m2[0],  m2[1],  m2[2],  m2[3]);
        *(float4*)(hb + 2 * HPLANE) = make_float4(q11[0], q11[1], q11[2], q11[3]);
        *(float4*)(hb + 3 * HPLANE) = make_float4(q22[0], q22[1], q22[2], q22[3]);
        *(float4*)(hb + 4 * HPLANE) = make_float4(q12[0], q12[1], q12[2], q12[3]);
    }
    __syncthreads();

    // ---- Phase 3: vertical 11-tap blur + ssim, 8 output rows / thread ----
    const int col = tid & 63;
    const int r0  = (tid >> 6) << 3;   // 0,8,16,24

    float acc0[8], acc1[8], acc2[8], acc3[8], acc4[8];
    #pragma unroll
    for (int j = 0; j < 8; j++) {
        acc0[j] = 0.f; acc1[j] = 0.f; acc2[j] = 0.f; acc3[j] = 0.f; acc4[j] = 0.f;
    }

    #pragma unroll
    for (int i = 0; i < 18; i++) {
        const float* hp = sh + (r0 + i) * TILE_W + col;
        float h0 = hp[0 * HPLANE];
        float h1 = hp[1 * HPLANE];
        float h2 = hp[2 * HPLANE];
        float h3 = hp[3 * HPLANE];
        float h4 = hp[4 * HPLANE];
        #pragma unroll
        for (int j = 0; j < 8; j++) {
            int k = i - j;
            if (k >= 0 && k < 11) {
                float w = gw(k);
                acc0[j] = fmaf(h0, w, acc0[j]);
                acc1[j] = fmaf(h1, w, acc1[j]);
                acc2[j] = fmaf(h2, w, acc2[j]);
                acc3[j] = fmaf(h3, w, acc3[j]);
                acc4[j] = fmaf(h4, w, acc4[j]);
            }
        }
    }

    const float C1 = 0.0001f;   // 0.01^2
    const float C2 = 0.0009f;   // 0.03^2
    float tsum = 0.f;
    #pragma unroll
    for (int j = 0; j < 8; j++) {
        float mu1 = acc0[j], mu2 = acc1[j];
        float mu1s = mu1 * mu1, mu2s = mu2 * mu2, mu12 = mu1 * mu2;
        float sA  = acc2[j] - mu1s;
        float sB  = acc3[j] - mu2s;
        float sAB = acc4[j] - mu12;
        float num = (2.f * mu12 + C1) * (2.f * sAB + C2);
        float den = (mu1s + mu2s + C1) * (sA + sB + C2);
        tsum += __fdividef(num, den);
    }

    // ---- Reduction: warp shuffle -> block -> global atomic ----
    #pragma unroll
    for (int off = 16; off; off >>= 1)
        tsum += __shfl_xor_sync(0xffffffffu, tsum, off);

    __syncthreads();   // everyone done reading sh / phase-3 smem before reuse of smem[0..7]
    if ((tid & 31) == 0) smem[tid >> 5] = tsum;
    __syncthreads();
    if (tid == 0) {
        float bs = 0.f;
        #pragma unroll
        for (int i = 0; i < NTHREADS / 32; i++) bs += smem[i];
        atomicAdd(&g_sum, (double)bs);
    }
}

__global__ void ssim_fin(float* out, double inv_n) {
    out[0] = 1.0f - (float)(g_sum * inv_n);
}

extern "C" void kernel_launch(void* const* d_in, const int* in_sizes, int n_in,
                              void* d_out, int out_size) {
    const float* img1 = (const float*)d_in[0];
    const float* img2 = (const float*)d_in[1];
    (void)n_in; (void)out_size;

    int planes = in_sizes[0] / (IMG * IMG);   // N*C = 96

    cudaFuncSetAttribute(ssim_main, cudaFuncAttributeMaxDynamicSharedMemorySize,
                         SMEM_BYTES);

    ssim_zero<<<1, 1>>>();
    dim3 grid(IMG / TILE_W, IMG / TILE_H, planes);
    ssim_main<<<grid, NTHREADS, SMEM_BYTES>>>(img1, img2);
    double inv_n = 1.0 / ((double)planes * IMG * IMG);
    ssim_fin<<<1, 1>>>((float*)d_out, inv_n);
}